// round 6
// baseline (speedup 1.0000x reference)
#include <cuda_runtime.h>
#include <cuda_bf16.h>
#include <stdint.h>

// ============================================================================
// MPS chain on sm_103 (baseline ISA): warp-resident state + mma.sync bf16
// 2-limb split. 128 CTAs x (8 compute warps + 1 producer warp).
// ============================================================================

#define NMID   62
#define NCHUNK 124           // hi,lo W chunk per step
#define NBUF   3
#define TILE_BYTES 65536     // 128 rows (r) x 512 B (256 k-cols bf16)
#define SMEM_BYTES (2048 + NBUF * TILE_BYTES)

__device__ __align__(128) unsigned char g_wimg[(size_t)NCHUNK * TILE_BYTES];

__device__ __forceinline__ uint32_t smem_u32(const void* p) {
    uint32_t a;
    asm("{ .reg .u64 t; cvta.to.shared.u64 t, %1; cvt.u32.u64 %0, t; }" : "=r"(a) : "l"(p));
    return a;
}

#define MBAR_INIT(a, c) asm volatile("mbarrier.init.shared.b64 [%0], %1;" :: "r"(a), "r"(c) : "memory")
#define MBAR_ARRIVE(a)  asm volatile("mbarrier.arrive.shared.b64 _, [%0];" :: "r"(a) : "memory")
#define MBAR_EXPECT(a, tx) asm volatile("mbarrier.arrive.expect_tx.shared.b64 _, [%0], %1;" :: "r"(a), "r"(tx) : "memory")
#define MBAR_WAIT(a, par) do { \
    uint32_t _d; \
    asm volatile("{ .reg .pred p; mbarrier.try_wait.parity.acquire.cta.shared::cta.b64 p, [%1], %2; selp.b32 %0,1,0,p; }" \
        : "=r"(_d) : "r"(a), "r"(par) : "memory"); \
    if (!_d) { \
        asm volatile("{ .reg .pred P1; W%=: mbarrier.try_wait.parity.acquire.cta.shared::cta.b64 P1, [%0], %1, 0x989680; @P1 bra.uni D%=; bra.uni W%=; D%=: }" \
            :: "r"(a), "r"(par) : "memory"); \
    } } while (0)

// pack_bf16x2(lo, hi): result low half = bf16(lo), high half = bf16(hi)
__device__ __forceinline__ uint32_t pack_bf16x2(float lo, float hi) {
    uint32_t r;
    asm("cvt.rn.bf16x2.f32 %0, %1, %2;" : "=r"(r) : "f"(hi), "f"(lo));
    return r;
}
__device__ __forceinline__ float lo_as_f32(uint32_t p) { return __uint_as_float(p << 16); }
__device__ __forceinline__ float hi_as_f32(uint32_t p) { return __uint_as_float(p & 0xFFFF0000u); }

// mma.sync m16n8k16 row.col f32.bf16.bf16.f32, accumulate in place
#define MMA_ACC(C, A, b0, b1) \
    asm volatile("mma.sync.aligned.m16n8k16.row.col.f32.bf16.bf16.f32 " \
        "{%0,%1,%2,%3}, {%4,%5,%6,%7}, {%8,%9}, {%0,%1,%2,%3};" \
        : "+f"((C)[0]), "+f"((C)[1]), "+f"((C)[2]), "+f"((C)[3]) \
        : "r"((A)[0]), "r"((A)[1]), "r"((A)[2]), "r"((A)[3]), "r"(b0), "r"(b1))
// first product of a step: zero accumulator (re-initializes C)
#define MMA_ZRO(C, A, b0, b1) \
    asm volatile("mma.sync.aligned.m16n8k16.row.col.f32.bf16.bf16.f32 " \
        "{%0,%1,%2,%3}, {%4,%5,%6,%7}, {%8,%9}, {%10,%10,%10,%10};" \
        : "=f"((C)[0]), "=f"((C)[1]), "=f"((C)[2]), "=f"((C)[3]) \
        : "r"((A)[0]), "r"((A)[1]), "r"((A)[2]), "r"((A)[3]), "r"(b0), "r"(b1), "f"(0.0f))

#define LDSM4(r0, r1, r2, r3, a) \
    asm volatile("ldmatrix.sync.aligned.m8n8.x4.shared.b16 {%0,%1,%2,%3}, [%4];" \
        : "=r"(r0), "=r"(r1), "=r"(r2), "=r"(r3) : "r"(a))

// ---------------- prep: split W into bf16 hi/lo, transpose, swizzle ---------
// Image chunk 2s (hi) / 2s+1 (lo): Wt[r][k] = W[k][r], k = 2l+i, rows of 512B,
// 16B-chunk swizzle: phys = r*512 + (kbyte ^ ((r&7)<<4))
__global__ void prep_kernel(const float* __restrict__ w_mid) {
    int idx = blockIdx.x * 256 + threadIdx.x;   // (s, l, r)
    if (idx >= NMID * 128 * 128) return;
    int s = idx >> 14, l = (idx >> 7) & 127, r = idx & 127;
    const float* base = w_mid + ((size_t)(s * 128 + l)) * 256 + r;
    float w0 = base[0], w1 = base[128];         // i = 0, 1
    uint32_t hp = pack_bf16x2(w0, w1);
    float l0 = w0 - lo_as_f32(hp), l1 = w1 - hi_as_f32(hp);
    uint32_t lp = pack_bf16x2(l0, l1);
    uint32_t kbyte = 4u * (uint32_t)l;           // k = 2l, pair (i=0, i=1)
    uint32_t phys = (uint32_t)r * 512 + (kbyte ^ (((uint32_t)r & 7) << 4));
    *(uint32_t*)(g_wimg + (size_t)(2 * s) * TILE_BYTES + phys) = hp;
    *(uint32_t*)(g_wimg + (size_t)(2 * s + 1) * TILE_BYTES + phys) = lp;
}

// ------------------------------- main kernel --------------------------------
__global__ void __launch_bounds__(288, 1) mps_kernel(
    const float* __restrict__ x, const float* __restrict__ w_first,
    const float* __restrict__ w_last, float* __restrict__ out) {
    extern __shared__ __align__(16) unsigned char smem[];
    uint32_t sb = smem_u32(smem);
    uint32_t bufb = (sb + 1024 + 1023) & ~1023u;
    int tid = threadIdx.x, wid = tid >> 5, lane = tid & 31;
    uint32_t full_b = sb, cons_b = sb + 32;

    if (tid == 0) {
        for (int i = 0; i < NBUF; i++) { MBAR_INIT(full_b + 8 * i, 1); MBAR_INIT(cons_b + 8 * i, 8); }
    }
    __syncthreads();

    if (wid == 8) {                        // ---------- producer ----------
        if (lane == 0) {
            for (int c = 0; c < NCHUNK; ++c) {
                uint32_t slot = c % 3;
                MBAR_WAIT(cons_b + 8 * slot, 1u ^ ((uint32_t)(c / 3) & 1u));
                MBAR_EXPECT(full_b + 8 * slot, TILE_BYTES);
                asm volatile("cp.async.bulk.shared::cluster.global.mbarrier::complete_tx::bytes [%0], [%1], %2, [%3];"
                    :: "r"(bufb + slot * TILE_BYTES), "l"(g_wimg + (size_t)c * TILE_BYTES),
                       "r"(TILE_BYTES), "r"(full_b + 8 * slot) : "memory");
            }
        }
        return;
    }

    // ---------- 8 compute warps: warp w owns rows [w*16, w*16+16), all cols
    int g = lane >> 2, q = lane & 3;
    int row0 = blockIdx.x * 128 + wid * 16 + g;
    int row1 = row0 + 8;
    const float* x0p = x + (size_t)row0 * 128;
    const float* x1p = x + (size_t)row1 * 128;

    float Co[64], Cn[64];                  // [ntile][4] fp32 fragments
    #pragma unroll
    for (int i = 0; i < 64; i++) Co[i] = 0.0f;
    {   // site-0 init: v[b,r] = x0*wf[0][r] + x1*wf[1][r], r in {0,1}
        float xa0 = x0p[0], xb0 = x0p[1], xa1 = x1p[0], xb1 = x1p[1];
        float wf0 = w_first[0], wf1 = w_first[1], wf2 = w_first[2], wf3 = w_first[3];
        if (q == 0) {
            Co[0] = xa0 * wf0 + xb0 * wf2;  Co[1] = xa0 * wf1 + xb0 * wf3;
            Co[2] = xa1 * wf0 + xb1 * wf2;  Co[3] = xa1 * wf1 + xb1 * wf3;
        }
    }
    float nxa0 = x0p[2], nxb0 = x0p[3], nxa1 = x1p[2], nxb1 = x1p[3];

    uint32_t rl  = ((uint32_t)(lane >> 4) << 3) + (lane & 7);   // ldmatrix row-in-pair
    uint32_t kbl = ((uint32_t)(lane >> 3) & 1u) << 4;           // k-half select
    uint32_t swz = (rl & 7) << 4;
    int src1 = (lane & ~3) | (q >> 1);
    int src2 = src1 + 2;

    #pragma unroll 1
    for (int m = 0; m < NMID; ++m) {
        int ch = 2 * m, cl = 2 * m + 1;
        uint32_t hib = bufb + (uint32_t)(ch % 3) * TILE_BYTES;
        uint32_t lob = bufb + (uint32_t)(cl % 3) * TILE_BYTES;
        MBAR_WAIT(full_b + 8 * (ch % 3), (uint32_t)(ch / 3) & 1u);
        MBAR_WAIT(full_b + 8 * (cl % 3), (uint32_t)(cl / 3) & 1u);
        float xa0 = nxa0, xb0 = nxb0, xa1 = nxa1, xb1 = nxb1;
        nxa0 = x0p[(m + 2) * 2]; nxb0 = x0p[(m + 2) * 2 + 1];
        nxa1 = x1p[(m + 2) * 2]; nxb1 = x1p[(m + 2) * 2 + 1];

        #pragma unroll
        for (int kc = 0; kc < 16; ++kc) {
            // ---- A fragments from old state: v values live in C tile kc ----
            float c0g = Co[kc*4+0], c1g = Co[kc*4+1], c0h = Co[kc*4+2], c1h = Co[kc*4+3];
            float t0, t1;
            t0 = __shfl_sync(0xffffffffu, c0g, src1); t1 = __shfl_sync(0xffffffffu, c1g, src1);
            float v1g = (q & 1) ? t1 : t0;
            t0 = __shfl_sync(0xffffffffu, c0h, src1); t1 = __shfl_sync(0xffffffffu, c1h, src1);
            float v1h = (q & 1) ? t1 : t0;
            t0 = __shfl_sync(0xffffffffu, c0g, src2); t1 = __shfl_sync(0xffffffffu, c1g, src2);
            float v2g = (q & 1) ? t1 : t0;
            t0 = __shfl_sync(0xffffffffu, c0h, src2); t1 = __shfl_sync(0xffffffffu, c1h, src2);
            float v2h = (q & 1) ? t1 : t0;

            uint32_t Ah[4], Al[4];
            {
                float u0 = v1g * xa0, u1 = v1g * xb0;
                Ah[0] = pack_bf16x2(u0, u1);
                Al[0] = pack_bf16x2(u0 - lo_as_f32(Ah[0]), u1 - hi_as_f32(Ah[0]));
                u0 = v1h * xa1; u1 = v1h * xb1;
                Ah[1] = pack_bf16x2(u0, u1);
                Al[1] = pack_bf16x2(u0 - lo_as_f32(Ah[1]), u1 - hi_as_f32(Ah[1]));
                u0 = v2g * xa0; u1 = v2g * xb0;
                Ah[2] = pack_bf16x2(u0, u1);
                Al[2] = pack_bf16x2(u0 - lo_as_f32(Ah[2]), u1 - hi_as_f32(Ah[2]));
                u0 = v2h * xa1; u1 = v2h * xb1;
                Ah[3] = pack_bf16x2(u0, u1);
                Al[3] = pack_bf16x2(u0 - lo_as_f32(Ah[3]), u1 - hi_as_f32(Ah[3]));
            }
            uint32_t koff = ((uint32_t)kc * 32 + kbl) ^ swz;
            #pragma unroll
            for (int p = 0; p < 8; ++p) {
                uint32_t roff = ((uint32_t)p * 16 + rl) * 512;
                uint32_t bh0, bh1, bh2, bh3, bl0, bl1, bl2, bl3;
                LDSM4(bh0, bh1, bh2, bh3, hib + roff + koff);
                LDSM4(bl0, bl1, bl2, bl3, lob + roff + koff);
                float* C0 = &Cn[(2 * p) * 4];
                float* C1 = &Cn[(2 * p + 1) * 4];
                if (kc == 0) { MMA_ZRO(C0, Ah, bh0, bh1); MMA_ZRO(C1, Ah, bh2, bh3); }
                else         { MMA_ACC(C0, Ah, bh0, bh1); MMA_ACC(C1, Ah, bh2, bh3); }
                MMA_ACC(C0, Al, bh0, bh1);
                MMA_ACC(C0, Ah, bl0, bl1);
                MMA_ACC(C1, Al, bh2, bh3);
                MMA_ACC(C1, Ah, bl2, bl3);
            }
        }
        if (lane == 0) { MBAR_ARRIVE(cons_b + 8 * (ch % 3)); MBAR_ARRIVE(cons_b + 8 * (cl % 3)); }
        #pragma unroll
        for (int i = 0; i < 64; i++) Co[i] = Cn[i];
    }

    // final: out[b] = sum_{l<2} v[b,l] * (w_last[l,0]*xA + w_last[l,1]*xB)
    // (x site 63 sits in nx* from the last prefetch)
    if (q == 0) {
        float wl00 = w_last[0], wl01 = w_last[1], wl10 = w_last[2], wl11 = w_last[3];
        float tg0 = wl00 * nxa0 + wl01 * nxb0;
        float tg1 = wl10 * nxa0 + wl11 * nxb0;
        out[row0] = Co[0] * tg0 + Co[1] * tg1;
        float th0 = wl00 * nxa1 + wl01 * nxb1;
        float th1 = wl10 * nxa1 + wl11 * nxb1;
        out[row1] = Co[2] * th0 + Co[3] * th1;
    }
}

extern "C" void kernel_launch(void* const* d_in, const int* in_sizes, int n_in,
                              void* d_out, int out_size) {
    const float* x       = (const float*)d_in[0];
    const float* w_first = (const float*)d_in[1];
    const float* w_mid   = (const float*)d_in[2];
    const float* w_last  = (const float*)d_in[3];
    cudaFuncSetAttribute(mps_kernel, cudaFuncAttributeMaxDynamicSharedMemorySize, SMEM_BYTES);
    prep_kernel<<<(NMID * 128 * 128 + 255) / 256, 256>>>(w_mid);
    mps_kernel<<<128, 288, SMEM_BYTES>>>(x, w_first, w_last, (float*)d_out);
}